// round 5
// baseline (speedup 1.0000x reference)
#include <cuda_runtime.h>
#include <cstdint>

#define SEQ   2048
#define BATCH 2
#define NH    16
#define DH    128
#define DM    2048
#define MTOT  (BATCH*SEQ)   // 4096

// Scratch (device globals — allocation-free per harness rules).
// g_q: pre-scaled (1/sqrt(128)), RN-tf32 rounded, d-permuted within 8-groups.
// g_k: RN-tf32 rounded, d-permuted.  g_v: RN-tf32 rounded, natural d order.
__device__ float g_q [BATCH*NH*SEQ*DH];   // [B,H,S,D]
__device__ float g_k [BATCH*NH*SEQ*DH];
__device__ float g_v [BATCH*NH*SEQ*DH];
__device__ float g_ao[BATCH*SEQ*DM];      // attention out, [B,S,H*D] (full fp32)

__device__ __forceinline__ float to_tf32(float x) {
    asm("cvt.rna.tf32.f32 %0, %0;" : "+f"(x));
    return x;
}

__device__ __forceinline__ void mma_tf32(float* c, const uint32_t* a, const uint32_t* b) {
    asm volatile(
        "mma.sync.aligned.m16n8k8.row.col.f32.tf32.tf32.f32 "
        "{%0,%1,%2,%3}, {%4,%5,%6,%7}, {%8,%9}, {%0,%1,%2,%3};"
        : "+f"(c[0]), "+f"(c[1]), "+f"(c[2]), "+f"(c[3])
        : "r"(a[0]), "r"(a[1]), "r"(a[2]), "r"(a[3]), "r"(b[0]), "r"(b[1]));
}

__device__ __forceinline__ void cp16(uint32_t dst, const void* src) {
    asm volatile("cp.async.cg.shared.global [%0], [%1], 16;" :: "r"(dst), "l"(src));
}
__device__ __forceinline__ void cp_commit() { asm volatile("cp.async.commit_group;"); }
__device__ __forceinline__ void cp_wait1()  { asm volatile("cp.async.wait_group 1;"); }

// ---------------------------------------------------------------------------
// TF32 tensor-core GEMM. 128x128 CTA tile, BK=16, 256 threads (8 warps 2x4).
// Smem stored k-PAIRED: float2 holds (k, k+4) so fragment loads are LDS.64.
//   kp(k) = (k&3) + ((k>>3)<<2)   (8 rows),  half(k) = (k>>2)&1
// MODE 0: C = x @ W_qkv + b_qkv -> g_q/g_k/g_v with attention pre-bake.
// MODE 1: C = g_ao @ W_out + b_out -> d_out.
// ---------------------------------------------------------------------------
#define AP2 132   // float2 pitch (== 4 mod 16 -> conflict-free LDS.64 frags)
#define BP2 132

template<int MODE>
__global__ __launch_bounds__(256, 2)
void tgemm(const float* __restrict__ A,
           const float* __restrict__ Bg,
           const float* __restrict__ bias,
           float* __restrict__ C,
           int K, int N)
{
    __shared__ float2 As2[8*AP2];
    __shared__ float2 Bs2[8*BP2];
    float* Asf = (float*)As2;
    float* Bsf = (float*)Bs2;

    const int tid  = threadIdx.x;
    const int bm   = blockIdx.y, bn = blockIdx.x;
    const int lane = tid & 31;
    const int wid  = tid >> 5;
    const int wm   = wid & 1;
    const int wn   = wid >> 1;
    const int gid  = lane >> 2;
    const int tig  = lane & 3;

    const int arow = tid >> 1;
    const int acol = (tid & 1) * 8;
    const int brow = tid >> 4;
    const int bcol = (tid & 15) * 4;

    // store indices for this thread's loads
    const int kpb   = (brow & 3) + ((brow >> 3) << 2);
    const int halfb = (brow >> 2) & 1;

    const float* Ap    = (MODE == 1) ? (const float*)g_ao : A;
    const float* Aload = Ap + (size_t)(bm*128 + arow)*K + acol;
    const float* Bload = Bg + (size_t)brow*N + bn*128 + bcol;

    float acc[4][4][4];
    #pragma unroll
    for (int mi = 0; mi < 4; mi++)
        #pragma unroll
        for (int nj = 0; nj < 4; nj++)
            #pragma unroll
            for (int f = 0; f < 4; f++) acc[mi][nj][f] = 0.f;

    // ---- store helpers ----
    auto storeA = [&](int i, float v) {   // i = 0..7, k = acol+i
        const int kg   = acol + i;
        const int kp   = (kg & 3) + ((kg >> 3) << 2);
        const int half = (kg >> 2) & 1;
        Asf[(kp*AP2 + arow)*2 + half] = to_tf32(v);
    };
    auto storeB = [&](int i, float v, int coff) {  // col = bcol+i+coff
        Bsf[(kpb*BP2 + bcol + i + coff)*2 + halfb] = to_tf32(v);
    };

    {
        float4 a0 = *(const float4*)(Aload);
        float4 a1 = *(const float4*)(Aload + 4);
        float4 b0 = *(const float4*)(Bload);
        float4 b1 = *(const float4*)(Bload + 64);
        storeA(0, a0.x); storeA(1, a0.y); storeA(2, a0.z); storeA(3, a0.w);
        storeA(4, a1.x); storeA(5, a1.y); storeA(6, a1.z); storeA(7, a1.w);
        storeB(0, b0.x, 0);  storeB(1, b0.y, 0);  storeB(2, b0.z, 0);  storeB(3, b0.w, 0);
        storeB(0, b1.x, 64); storeB(1, b1.y, 64); storeB(2, b1.z, 64); storeB(3, b1.w, 64);
    }
    __syncthreads();

    for (int k0 = 16; k0 <= K; k0 += 16) {
        const bool nxt = k0 < K;
        float4 na0, na1, nb0, nb1;
        if (nxt) {
            na0 = *(const float4*)(Aload + k0);
            na1 = *(const float4*)(Aload + k0 + 4);
            nb0 = *(const float4*)(Bload + (size_t)k0*N);
            nb1 = *(const float4*)(Bload + (size_t)k0*N + 64);
        }

        #pragma unroll
        for (int ks = 0; ks < 2; ks++) {
            uint32_t af[4][4];
            uint32_t bf[4][2];
            #pragma unroll
            for (int mi = 0; mi < 4; mi++) {
                const int r = wm*64 + mi*16 + gid;
                const float2 aLo = As2[(ks*4 + tig)*AP2 + r];
                const float2 aHi = As2[(ks*4 + tig)*AP2 + r + 8];
                af[mi][0] = __float_as_uint(aLo.x);
                af[mi][1] = __float_as_uint(aHi.x);
                af[mi][2] = __float_as_uint(aLo.y);
                af[mi][3] = __float_as_uint(aHi.y);
            }
            #pragma unroll
            for (int nj = 0; nj < 4; nj++) {
                const int c = wn*32 + nj*8 + gid;
                const float2 bb2 = Bs2[(ks*4 + tig)*BP2 + c];
                bf[nj][0] = __float_as_uint(bb2.x);
                bf[nj][1] = __float_as_uint(bb2.y);
            }
            #pragma unroll
            for (int mi = 0; mi < 4; mi++)
                #pragma unroll
                for (int nj = 0; nj < 4; nj++)
                    mma_tf32(acc[mi][nj], af[mi], bf[nj]);
        }

        if (nxt) {
            __syncthreads();
            storeA(0, na0.x); storeA(1, na0.y); storeA(2, na0.z); storeA(3, na0.w);
            storeA(4, na1.x); storeA(5, na1.y); storeA(6, na1.z); storeA(7, na1.w);
            storeB(0, nb0.x, 0);  storeB(1, nb0.y, 0);  storeB(2, nb0.z, 0);  storeB(3, nb0.w, 0);
            storeB(0, nb1.x, 64); storeB(1, nb1.y, 64); storeB(2, nb1.z, 64); storeB(3, nb1.w, 64);
            __syncthreads();
        }
    }

    // ---- epilogue ----
    float2 bb[4];
    #pragma unroll
    for (int nj = 0; nj < 4; nj++)
        bb[nj] = *(const float2*)&bias[bn*128 + wn*32 + nj*8 + tig*2];

    if (MODE == 0) {
        const int ncol0 = bn*128;
        const int which = ncol0 >> 11;           // 0=q 1=k 2=v
        const int h     = (ncol0 & 2047) >> 7;
        const float qscale = 0.088388347648318447f;  // 1/sqrt(128)
        float* dst = (which == 0) ? g_q : (which == 1) ? g_k : g_v;
        // d-permutation within 8-group: logical dd -> mem ((dd&3)<<1)|(dd>>2)
        const int dd0 = tig*2, dd1 = tig*2 + 1;
        const int mm0 = ((dd0 & 3) << 1) | (dd0 >> 2);
        const int mm1 = ((dd1 & 3) << 1) | (dd1 >> 2);
        #pragma unroll
        for (int mi = 0; mi < 4; mi++) {
            #pragma unroll
            for (int half = 0; half < 2; half++) {
                const int m = bm*128 + wm*64 + mi*16 + gid + half*8;
                const int b = m >> 11;
                const int s = m & 2047;
                float* drow = dst + ((size_t)(b*NH + h)*SEQ + s)*DH;
                #pragma unroll
                for (int nj = 0; nj < 4; nj++) {
                    float v0 = acc[mi][nj][half*2+0] + bb[nj].x;
                    float v1 = acc[mi][nj][half*2+1] + bb[nj].y;
                    if (which == 0) { v0 *= qscale; v1 *= qscale; }
                    v0 = to_tf32(v0); v1 = to_tf32(v1);
                    const int base = wn*32 + nj*8;
                    if (which == 2) {
                        float2 v; v.x = v0; v.y = v1;
                        *(float2*)&drow[base + tig*2] = v;
                    } else {
                        drow[base + mm0] = v0;
                        drow[base + mm1] = v1;
                    }
                }
            }
        }
    } else {
        #pragma unroll
        for (int mi = 0; mi < 4; mi++) {
            #pragma unroll
            for (int half = 0; half < 2; half++) {
                const int m = bm*128 + wm*64 + mi*16 + gid + half*8;
                float* crow = C + (size_t)m*N + bn*128;
                #pragma unroll
                for (int nj = 0; nj < 4; nj++) {
                    const int n = wn*32 + nj*8 + tig*2;
                    float2 v;
                    v.x = acc[mi][nj][half*2+0] + bb[nj].x;
                    v.y = acc[mi][nj][half*2+1] + bb[nj].y;
                    *(float2*)&crow[n] = v;
                }
            }
        }
    }
}

// ---------------------------------------------------------------------------
// Tensor-core flash attention (TF32). One CTA per (128 q-rows, h, b).
// Q/K arrive pre-rounded + d-permuted -> fragment pairs are contiguous LDS.64.
// V pre-rounded. NO in-smem conversion pass. cp.async double-buffered K/V.
// ---------------------------------------------------------------------------
#define QP  136   // Q pitch in floats (QP/2=68 ≡ 4 mod 16 -> conflict-free LDS.64)
#define KP  136
#define VP  136
#define ATTN_SMEM ((128*QP + 2*64*KP + 2*64*VP) * 4)   // 208896 B

__global__ __launch_bounds__(256, 1)
void attn_tc()
{
    extern __shared__ float sm[];
    float* Qs = sm;                   // 128 x QP
    float* Ks = Qs + 128*QP;          // 2 x 64 x KP
    float* Vs = Ks + 2*64*KP;         // 2 x 64 x VP

    const int qt  = (int)(gridDim.x - 1 - blockIdx.x);   // heavy tiles first
    const int h   = blockIdx.y, b = blockIdx.z;
    const int tid = threadIdx.x;
    const int lane = tid & 31;
    const int wid  = tid >> 5;
    const int gid  = lane >> 2;   // 0..7
    const int tig  = lane & 3;    // 0..3

    const float* Qg = g_q + ((size_t)(b*NH + h)*SEQ + qt*128)*DH;
    const float* Kg = g_k + ((size_t)(b*NH + h)*SEQ)*DH;
    const float* Vg = g_v + ((size_t)(b*NH + h)*SEQ)*DH;

    const uint32_t smb   = (uint32_t)__cvta_generic_to_shared(sm);
    const uint32_t ks_b  = smb + 128*QP*4;
    const uint32_t vs_b  = ks_b + 2*64*KP*4;

    const int nkt = 2*qt + 2;

    // ---- issue cp.async for K/V tile 0 ----
    {
        #pragma unroll
        for (int t = 0; t < 8; t++) {
            const int e = tid + t*256;
            const int r = e >> 5, c = (e & 31) << 2;
            cp16(ks_b + (uint32_t)(r*KP + c)*4, Kg + r*128 + c);
            cp16(vs_b + (uint32_t)(r*VP + c)*4, Vg + r*128 + c);
        }
        cp_commit();
    }

    // ---- copy Q tile (already scaled/rounded/permuted) ----
    for (int idx = tid; idx < 128*32; idx += 256) {
        const int r = idx >> 5, c = (idx & 31) << 2;
        *(float4*)(Qs + r*QP + c) = *(const float4*)(Qg + r*128 + c);
    }
    __syncthreads();

    // ---- Q fragments in registers: 16 k-blocks x 4 regs (LDS.64 pairs) ----
    uint32_t qa[16][4];
    {
        const float2* Q2 = (const float2*)Qs;
        const int r0 = wid*16 + gid;
        #pragma unroll
        for (int kb = 0; kb < 16; kb++) {
            const float2 qLo = Q2[(size_t)r0*(QP/2) + kb*4 + tig];
            const float2 qHi = Q2[(size_t)(r0+8)*(QP/2) + kb*4 + tig];
            qa[kb][0] = __float_as_uint(qLo.x);
            qa[kb][1] = __float_as_uint(qHi.x);
            qa[kb][2] = __float_as_uint(qLo.y);
            qa[kb][3] = __float_as_uint(qHi.y);
        }
    }

    float oacc[16][4];
    #pragma unroll
    for (int nv = 0; nv < 16; nv++)
        #pragma unroll
        for (int f = 0; f < 4; f++) oacc[nv][f] = 0.f;
    float m0 = -1e30f, m1 = -1e30f, l0 = 0.f, l1 = 0.f;

    const int r0g = qt*128 + wid*16 + gid;
    const int r1g = r0g + 8;

    for (int kt = 0; kt < nkt; kt++) {
        if (kt + 1 < nkt) {
            const int nb = (kt + 1) & 1;
            const float* Kt = Kg + (size_t)(kt+1)*64*DH;
            const float* Vt = Vg + (size_t)(kt+1)*64*DH;
            const uint32_t kd = ks_b + (uint32_t)(nb*64*KP)*4;
            const uint32_t vd = vs_b + (uint32_t)(nb*64*VP)*4;
            #pragma unroll
            for (int t = 0; t < 8; t++) {
                const int e = tid + t*256;
                const int r = e >> 5, c = (e & 31) << 2;
                cp16(kd + (uint32_t)(r*KP + c)*4, Kt + r*128 + c);
                cp16(vd + (uint32_t)(r*VP + c)*4, Vt + r*128 + c);
            }
        }
        cp_commit();
        cp_wait1();
        __syncthreads();

        const int buf = kt & 1;
        const float2* K2 = (const float2*)(Ks + buf*64*KP);
        const float*  Vb = Vs + buf*64*VP;

        // ---- S = Q K^T (16x64 per warp), K frags via LDS.64 ----
        float sacc[8][4];
        #pragma unroll
        for (int nb = 0; nb < 8; nb++)
            #pragma unroll
            for (int f = 0; f < 4; f++) sacc[nb][f] = 0.f;

        #pragma unroll
        for (int ks = 0; ks < 16; ks++) {
            uint32_t bf[8][2];
            #pragma unroll
            for (int nb = 0; nb < 8; nb++) {
                const float2 kk = K2[(size_t)(nb*8 + gid)*(KP/2) + ks*4 + tig];
                bf[nb][0] = __float_as_uint(kk.x);
                bf[nb][1] = __float_as_uint(kk.y);
            }
            #pragma unroll
            for (int nb = 0; nb < 8; nb++)
                mma_tf32(sacc[nb], qa[ks], bf[nb]);
        }

        // ---- causal mask ----
        if (kt*64 + 63 > qt*128 + wid*16) {
            #pragma unroll
            for (int nb = 0; nb < 8; nb++) {
                const int c0 = kt*64 + nb*8 + 2*tig;
                const int c1 = c0 + 1;
                if (c0 > r0g) sacc[nb][0] = -1e30f;
                if (c1 > r0g) sacc[nb][1] = -1e30f;
                if (c0 > r1g) sacc[nb][2] = -1e30f;
                if (c1 > r1g) sacc[nb][3] = -1e30f;
            }
        }

        // ---- online softmax (warp-local rows, quad reductions) ----
        float mx0 = -1e30f, mx1 = -1e30f;
        #pragma unroll
        for (int nb = 0; nb < 8; nb++) {
            mx0 = fmaxf(mx0, fmaxf(sacc[nb][0], sacc[nb][1]));
            mx1 = fmaxf(mx1, fmaxf(sacc[nb][2], sacc[nb][3]));
        }
        mx0 = fmaxf(mx0, __shfl_xor_sync(0xffffffffu, mx0, 1));
        mx0 = fmaxf(mx0, __shfl_xor_sync(0xffffffffu, mx0, 2));
        mx1 = fmaxf(mx1, __shfl_xor_sync(0xffffffffu, mx1, 1));
        mx1 = fmaxf(mx1, __shfl_xor_sync(0xffffffffu, mx1, 2));

        const float mn0 = fmaxf(m0, mx0), mn1 = fmaxf(m1, mx1);
        const float cr0 = __expf(m0 - mn0), cr1 = __expf(m1 - mn1);
        m0 = mn0; m1 = mn1;

        float rs0 = 0.f, rs1 = 0.f;
        #pragma unroll
        for (int nb = 0; nb < 8; nb++) {
            sacc[nb][0] = __expf(sacc[nb][0] - mn0); rs0 += sacc[nb][0];
            sacc[nb][1] = __expf(sacc[nb][1] - mn0); rs0 += sacc[nb][1];
            sacc[nb][2] = __expf(sacc[nb][2] - mn1); rs1 += sacc[nb][2];
            sacc[nb][3] = __expf(sacc[nb][3] - mn1); rs1 += sacc[nb][3];
        }
        rs0 += __shfl_xor_sync(0xffffffffu, rs0, 1);
        rs0 += __shfl_xor_sync(0xffffffffu, rs0, 2);
        rs1 += __shfl_xor_sync(0xffffffffu, rs1, 1);
        rs1 += __shfl_xor_sync(0xffffffffu, rs1, 2);
        l0 = l0*cr0 + rs0;
        l1 = l1*cr1 + rs1;

        #pragma unroll
        for (int nv = 0; nv < 16; nv++) {
            oacc[nv][0] *= cr0; oacc[nv][1] *= cr0;
            oacc[nv][2] *= cr1; oacc[nv][3] *= cr1;
        }

        // ---- O += P V : P C-layout -> A-frags via quad shuffles ----
        const int srcLo = (lane & ~3) | (tig >> 1);
        const int srcHi = srcLo + 2;
        #pragma unroll
        for (int kb = 0; kb < 8; kb++) {
            const float t0 = __shfl_sync(0xffffffffu, sacc[kb][0], srcLo);
            const float t1 = __shfl_sync(0xffffffffu, sacc[kb][1], srcLo);
            const float t2 = __shfl_sync(0xffffffffu, sacc[kb][2], srcLo);
            const float t3 = __shfl_sync(0xffffffffu, sacc[kb][3], srcLo);
            const float u0 = __shfl_sync(0xffffffffu, sacc[kb][0], srcHi);
            const float u1 = __shfl_sync(0xffffffffu, sacc[kb][1], srcHi);
            const float u2 = __shfl_sync(0xffffffffu, sacc[kb][2], srcHi);
            const float u3 = __shfl_sync(0xffffffffu, sacc[kb][3], srcHi);
            uint32_t pa[4];
            pa[0] = __float_as_uint(to_tf32((tig & 1) ? t1 : t0));
            pa[1] = __float_as_uint(to_tf32((tig & 1) ? t3 : t2));
            pa[2] = __float_as_uint(to_tf32((tig & 1) ? u1 : u0));
            pa[3] = __float_as_uint(to_tf32((tig & 1) ? u3 : u2));
            #pragma unroll
            for (int nv = 0; nv < 16; nv++) {
                uint32_t vb[2];
                vb[0] = __float_as_uint(Vb[(size_t)(kb*8 + tig    )*VP + nv*8 + gid]);
                vb[1] = __float_as_uint(Vb[(size_t)(kb*8 + tig + 4)*VP + nv*8 + gid]);
                mma_tf32(oacc[nv], pa, vb);
            }
        }
        __syncthreads();
    }

    // ---- normalize + write [B,S,DM] ----
    const float inv0 = 1.0f / l0, inv1 = 1.0f / l1;
    float* O0 = g_ao + ((size_t)(b*SEQ + r0g))*DM + h*DH;
    float* O1 = O0 + (size_t)8*DM;
    #pragma unroll
    for (int nv = 0; nv < 16; nv++) {
        const int d = nv*8 + 2*tig;
        float2 v0, v1;
        v0.x = oacc[nv][0]*inv0; v0.y = oacc[nv][1]*inv0;
        v1.x = oacc[nv][2]*inv1; v1.y = oacc[nv][3]*inv1;
        *(float2*)&O0[d] = v0;
        *(float2*)&O1[d] = v1;
    }
}

// ---------------------------------------------------------------------------

extern "C" void kernel_launch(void* const* d_in, const int* in_sizes, int n_in,
                              void* d_out, int out_size)
{
    const float* x    = (const float*)d_in[0];
    const float* Wqkv = (const float*)d_in[1];
    const float* bqkv = (const float*)d_in[2];
    const float* Wout = (const float*)d_in[3];
    const float* bout = (const float*)d_in[4];
    float* out = (float*)d_out;

    cudaFuncSetAttribute(attn_tc, cudaFuncAttributeMaxDynamicSharedMemorySize, ATTN_SMEM);

    // 1) QKV projection -> g_q/g_k/g_v (pre-baked for attention)
    dim3 g1(3*DM/128, MTOT/128);
    tgemm<0><<<g1, 256>>>(x, Wqkv, bqkv, nullptr, DM, 3*DM);

    // 2) Causal attention -> g_ao
    dim3 g2(SEQ/128, NH, BATCH);
    attn_tc<<<g2, 256, ATTN_SMEM>>>();

    // 3) Output projection -> d_out
    dim3 g3(DM/128, MTOT/128);
    tgemm<1><<<g3, 256>>>(nullptr, Wout, bout, out, DM, DM);
}